// round 14
// baseline (speedup 1.0000x reference)
#include <cuda_runtime.h>
#include <cuda_bf16.h>
#include <math.h>

// EMA with SD, chunked parallel scan (round 14).
// x (T=8192, D=128); h_a0, h_sd0, alpha (N=32, D=128).
// out: (T, 2N, D) fp32, then hN_a (N,D), hN_sd (N,D).
//
// pass1 (r9's proven 12.9us, byte-identical): CS=128 chunks of LS=64, dual
//   independent 32-step sub-streams per thread, exact quadratic-map merge:
//     P' = W*P0 + P1,  A' = W*(A0 + (1-W)P0^2 - 2*P0*P1) + A1,  W = b^32
//   + cudaTriggerProgrammaticLaunchCompletion() at entry (PDL primary).
// pass2 (r12's proven winner, byte-identical math): CR=64 x LR=128, float2
//   lanes, per-block prefix fold of summaries 0..2c-1 (W=b^64), exact
//   replay with __stcs streaming stores, sqrt.approx.
//   PDL secondary: c==0 blocks skip the grid sync and start storing while
//   pass1 is still running; c>0 blocks cudaGridDependencySynchronize()
//   before touching g_P/g_A. Grid (NN, CR), c on the slow axis so low-c
//   blocks launch first.

#define TT 8192
#define DD 128
#define NN 32
#define CS 128
#define LS 64
#define HS 32           // pass1 sub-stream length
#define CR 64
#define LR 128
#define LANES (NN * DD)

__device__ float g_P[CS * LANES];
__device__ float g_A[CS * LANES];

__device__ __forceinline__ float sqrt_fast(float v) {
    float r;
    asm("sqrt.approx.f32 %0, %1;" : "=f"(r) : "f"(v));
    return r;
}

// ---------------------------------------------------------------- pass 1
// (r9's measured best + PDL trigger)
__global__ __launch_bounds__(64) void ema_pass1(
    const float* __restrict__ x,
    const float* __restrict__ alpha)
{
#if __CUDA_ARCH__ >= 900
    cudaTriggerProgrammaticLaunchCompletion();
#endif
    const int c  = blockIdx.x;           // 0..CS-1
    const int n  = blockIdx.y;           // 0..NN-1
    const int t  = threadIdx.x;          // 0..63
    const int idx = n * DD + 2 * t;

    const float2 al = *reinterpret_cast<const float2*>(alpha + idx);
    const float a0 = al.x, a1 = al.y;
    const float b0 = 1.0f - a0, b1 = 1.0f - a1;

    const float2* xp0 = reinterpret_cast<const float2*>(x + (size_t)c * LS * DD + 2 * t);
    const float2* xp1 = xp0 + (size_t)HS * (DD / 2);

    float g0a = 0.f, g0b = 0.f, A0a = 0.f, A0b = 0.f;   // stream 0
    float g1a = 0.f, g1b = 0.f, A1a = 0.f, A1b = 0.f;   // stream 1

#pragma unroll 8
    for (int i = 0; i < HS; ++i) {
        const float2 x0 = xp0[(size_t)i * (DD / 2)];
        const float2 x1 = xp1[(size_t)i * (DD / 2)];
        const float u0a = x0.x - g0a, u0b = x0.y - g0b;
        const float u1a = x1.x - g1a, u1b = x1.y - g1b;
        g0a = fmaf(a0, u0a, g0a);
        g0b = fmaf(a1, u0b, g0b);
        g1a = fmaf(a0, u1a, g1a);
        g1b = fmaf(a1, u1b, g1b);
        A0a = b0 * fmaf(a0, u0a * u0a, A0a);
        A0b = b1 * fmaf(a1, u0b * u0b, A0b);
        A1a = b0 * fmaf(a0, u1a * u1a, A1a);
        A1b = b1 * fmaf(a1, u1b * u1b, A1b);
    }

    float W0, W1;   // b^32 per lane
    {
        float p = b0 * b0; p *= p; p *= p; p *= p; W0 = p * p;
    }
    {
        float p = b1 * b1; p *= p; p *= p; p *= p; W1 = p * p;
    }
    const float Pm0 = fmaf(W0, g0a, g1a);
    const float Pm1 = fmaf(W1, g0b, g1b);
    const float Am0 = fmaf(W0, A0a, A1a)
                    + W0 * fmaf((1.0f - W0) * g0a, g0a, -2.0f * g0a * g1a);
    const float Am1 = fmaf(W1, A0b, A1b)
                    + W1 * fmaf((1.0f - W1) * g0b, g0b, -2.0f * g0b * g1b);

    const int s = c * LANES + idx;
    *reinterpret_cast<float2*>(g_P + s) = make_float2(Pm0, Pm1);
    *reinterpret_cast<float2*>(g_A + s) = make_float2(Am0, Am1);
}

// ---------------------------------------------------------------- pass 2
// (r12's winner; PDL secondary with per-block dependency skip for c==0)
__global__ __launch_bounds__(64) void ema_pass2(
    const float* __restrict__ x,
    const float* __restrict__ h_a0,
    const float* __restrict__ h_sd0,
    const float* __restrict__ alpha,
    float* __restrict__ out,
    int write_tail)
{
    const int n  = blockIdx.x;           // 0..NN-1 (fast axis)
    const int c  = blockIdx.y;           // 0..CR-1 (slow axis: low c launches first)
    const int d2 = threadIdx.x;          // 0..63
    const int idx = n * DD + 2 * d2;

    const float2 al = *reinterpret_cast<const float2*>(alpha + idx);
    const float a0 = al.x, a1 = al.y;
    const float b0 = 1.0f - a0, b1 = 1.0f - a1;

    // per-lane fold constants: W = b^64
    float W0, W1;
    {
        float p = b0 * b0; p *= p; p *= p; p *= p; p *= p; W0 = p * p;
    }
    {
        float p = b1 * b1; p *= p; p *= p; p *= p; p *= p; W1 = p * p;
    }
    const float Cq0 = W0 * (1.0f - W0), Cq1 = W1 * (1.0f - W1);
    const float m2W0 = -2.0f * W0,      m2W1 = -2.0f * W1;

    const float2 hav = *reinterpret_cast<const float2*>(h_a0 + idx);
    const float2 sdv = *reinterpret_cast<const float2*>(h_sd0 + idx);
    float ha0 = hav.x, ha1 = hav.y;
    float hv0 = sdv.x * sdv.x, hv1 = sdv.y * sdv.y;

    // entry state: fold summaries 0 .. 2c-1 (LS=64 granularity).
    // Only blocks that actually read g_P/g_A wait on the upstream grid.
    const int nfold = 2 * c;
    if (nfold > 0) {
#if __CUDA_ARCH__ >= 900
        cudaGridDependencySynchronize();
#endif
#pragma unroll 4
        for (int cc = 0; cc < nfold; ++cc) {
            const int s = cc * LANES + idx;
            const float2 P  = *reinterpret_cast<const float2*>(g_P + s);
            const float2 Aa = *reinterpret_cast<const float2*>(g_A + s);
            float hvn;
            hvn = fmaf(W0, hv0, fmaf(Cq0, ha0 * ha0, fmaf(m2W0 * P.x, ha0, Aa.x)));
            hv0 = fmaxf(hvn, 0.f);
            ha0 = fmaf(W0, ha0, P.x);
            hvn = fmaf(W1, hv1, fmaf(Cq1, ha1 * ha1, fmaf(m2W1 * P.y, ha1, Aa.y)));
            hv1 = fmaxf(hvn, 0.f);
            ha1 = fmaf(W1, ha1, P.y);
        }
    }

    // exact replay with streaming stores
    const float2* xp = reinterpret_cast<const float2*>(x + (size_t)c * LR * DD + 2 * d2);
    float2* obase = reinterpret_cast<float2*>(out + (size_t)c * LR * 2 * NN * DD + n * DD + 2 * d2);

#pragma unroll 8
    for (int i = 0; i < LR; ++i) {
        const float2 xv = xp[(size_t)i * (DD / 2)];
        const float u0 = xv.x - ha0;
        const float u1 = xv.y - ha1;
        ha0 = fmaf(a0, u0, ha0);
        ha1 = fmaf(a1, u1, ha1);
        hv0 = b0 * fmaf(a0, u0 * u0, hv0);
        hv1 = b1 * fmaf(a1, u1 * u1, hv1);
        float2* op = obase + (size_t)i * (NN * DD);      // i * 4096 float2
        __stcs(op, make_float2(ha0, ha1));
        __stcs(op + (NN * DD / 2), make_float2(sqrt_fast(hv0), sqrt_fast(hv1)));
    }

    // tail: final states from the last chunk's replay-exit state
    if (write_tail && c == CR - 1) {
        const size_t base = (size_t)TT * 2 * NN * DD;
        *reinterpret_cast<float2*>(out + base + idx) = make_float2(ha0, ha1);
        *reinterpret_cast<float2*>(out + base + LANES + idx) =
            make_float2(sqrt_fast(hv0), sqrt_fast(hv1));
    }
}

extern "C" void kernel_launch(void* const* d_in, const int* in_sizes, int n_in,
                              void* d_out, int out_size)
{
    const float* x     = (const float*)d_in[0];
    const float* h_a0  = (const float*)d_in[1];
    const float* h_sd0 = (const float*)d_in[2];
    const float* alpha = (const float*)d_in[3];
    float* out = (float*)d_out;

    const int main_elems = TT * 2 * NN * DD;
    const int write_tail = (out_size > main_elems) ? 1 : 0;

    dim3 grid1(CS, NN);
    ema_pass1<<<grid1, 64>>>(x, alpha);

    // pass2 as PDL secondary: may launch while pass1 runs; summary readers
    // are gated by cudaGridDependencySynchronize() in-kernel.
    cudaLaunchConfig_t cfg = {};
    cfg.gridDim  = dim3(NN, CR);
    cfg.blockDim = dim3(64);
    cfg.dynamicSmemBytes = 0;
    cfg.stream = 0;
    cudaLaunchAttribute attrs[1];
    attrs[0].id = cudaLaunchAttributeProgrammaticStreamSerialization;
    attrs[0].val.programmaticStreamSerializationAllowed = 1;
    cfg.attrs = attrs;
    cfg.numAttrs = 1;
    cudaLaunchKernelEx(&cfg, ema_pass2, x, h_a0, h_sd0, alpha, out, write_tail);
}